// round 1
// baseline (speedup 1.0000x reference)
#include <cuda_runtime.h>

// Problem constants (fixed shapes from reference)
#define B_    8
#define DIM   64
#define HID   128
#define HH    192
#define WW    192
#define HW    (HH*WW)          // 36864
#define TS    16               // interior tile
#define PAD   18               // TS + 2 halo
#define NPIX  (PAD*PAD)        // 324

// Scratch (no device mallocs allowed)
__device__ float g_xmean[B_*DIM];
__device__ float g_ker[B_*HID*9];

// ---------------------------------------------------------------------------
// Kernel 1: per-(b,c) spatial mean of x. grid = B*DIM blocks, 256 threads.
// ---------------------------------------------------------------------------
__global__ void k_mean(const float* __restrict__ x) {
    int bc = blockIdx.x;
    const float4* p = (const float4*)(x + (size_t)bc * HW);
    float s = 0.f;
    #pragma unroll 4
    for (int i = threadIdx.x; i < HW/4; i += 256) {
        float4 v = p[i];
        s += (v.x + v.y) + (v.z + v.w);
    }
    __shared__ float red[8];
    #pragma unroll
    for (int o = 16; o; o >>= 1) s += __shfl_down_sync(0xffffffffu, s, o);
    if ((threadIdx.x & 31) == 0) red[threadIdx.x >> 5] = s;
    __syncthreads();
    if (threadIdx.x < 32) {
        s = (threadIdx.x < 8) ? red[threadIdx.x] : 0.f;
        #pragma unroll
        for (int o = 4; o; o >>= 1) s += __shfl_down_sync(0xffffffffu, s, o);
        if (threadIdx.x == 0) g_xmean[bc] = s * (1.0f / (float)HW);
    }
}

// ---------------------------------------------------------------------------
// Kernel 2: dynamic 3x3 kernel generation.
// mean(h) = w_in @ mean(x) + b_in  (linearity of mean) -> no h materialization.
// grid = B blocks, 128 threads.
// ---------------------------------------------------------------------------
__global__ void k_gen(const float* __restrict__ w_in, const float* __restrict__ b_in,
                      const float* __restrict__ wg1,  const float* __restrict__ bg1,
                      const float* __restrict__ wg2,  const float* __restrict__ bg2) {
    int b = blockIdx.x;
    int t = threadIdx.x;  // 0..127
    __shared__ float xm[DIM], g0[HID], g1[HID];
    if (t < DIM) xm[t] = g_xmean[b*DIM + t];
    __syncthreads();
    {
        float s = b_in[t];
        #pragma unroll 8
        for (int c = 0; c < DIM; c++) s = fmaf(w_in[t*DIM + c], xm[c], s);
        g0[t] = s;   // == mean over spatial of h[b, t]
    }
    __syncthreads();
    {
        float s = bg1[t];
        #pragma unroll 8
        for (int c = 0; c < HID; c++) s = fmaf(wg1[t*HID + c], g0[c], s);
        g1[t] = s > 0.f ? s : 0.f;   // ReLU
    }
    __syncthreads();
    #pragma unroll
    for (int tt = 0; tt < 9; tt++) {
        int row = t*9 + tt;
        float s = bg2[row];
        #pragma unroll 8
        for (int c = 0; c < HID; c++) s = fmaf(wg2[row*HID + c], g1[c], s);
        g_ker[b*HID*9 + row] = s;
    }
}

// ---------------------------------------------------------------------------
// Kernel 3: fused  h = w_in@x + b_in  ->  per-sample depthwise 3x3 (SAME, zero
// pad on h) -> LeakyReLU(0.1) -> out = w_out@y + b_out.
// One CTA per 16x16 interior tile; h tile (128ch x 18x18) lives in SMEM.
// grid = (12, 12, 8), 256 threads, ~204KB dynamic smem.
//
// SMEM layout (floats):
//   sh_w   [8192]   : phase1 = w_in transposed [c][hid]; phase2 = w_out [hid][o]
//   sh_ker [1152]   : this sample's 128 x 9 dynamic kernels
//   sh_bin [128], sh_bout [64]
//   sh_h   [HID*NPIX = 41472]
// ---------------------------------------------------------------------------
extern __shared__ float smem[];

__global__ __launch_bounds__(256, 1)
void k_main(const float* __restrict__ x,
            const float* __restrict__ w_in,  const float* __restrict__ b_in,
            const float* __restrict__ w_out, const float* __restrict__ b_out,
            float* __restrict__ out) {
    float* sh_w    = smem;
    float* sh_ker  = smem + 8192;
    float* sh_bin  = sh_ker + HID*9;
    float* sh_bout = sh_bin + HID;
    float* sh_h    = sh_bout + 64;

    const int tid = threadIdx.x;
    const int b   = blockIdx.z;
    const int tx0 = blockIdx.x * TS, ty0 = blockIdx.y * TS;

    // --- load phase-1 weights: w_in transposed so inner loop does LDS.128 ---
    for (int i = tid; i < HID*DIM; i += 256) {
        int o = i / DIM, c = i % DIM;
        sh_w[c*HID + o] = w_in[i];
    }
    if (tid < HID) sh_bin[tid]  = b_in[tid];
    if (tid < 64)  sh_bout[tid] = b_out[tid];
    for (int i = tid; i < HID*9; i += 256) sh_ker[i] = g_ker[b*HID*9 + i];
    __syncthreads();

    // ------------------------- Phase 1: h into SMEM -------------------------
    const float* xb = x + (size_t)b * DIM * HW;
    for (int it = 0; it < 2; it++) {
        int pp = tid + it*256;
        if (pp >= NPIX) break;
        int py = pp / PAD, px = pp % PAD;
        int gy = ty0 + py - 1, gx = tx0 + px - 1;
        bool valid = (gy >= 0) & (gy < HH) & (gx >= 0) & (gx < WW);

        float xv[DIM];
        const float* xp = xb + gy*WW + gx;
        #pragma unroll
        for (int c = 0; c < DIM; c++) xv[c] = valid ? xp[(size_t)c * HW] : 0.f;

        #pragma unroll 1
        for (int hb = 0; hb < HID; hb += 16) {
            float acc[16];
            #pragma unroll
            for (int i = 0; i < 16; i++) acc[i] = valid ? sh_bin[hb + i] : 0.f;
            const float* wbase = sh_w + hb;
            #pragma unroll 8
            for (int c = 0; c < DIM; c++) {
                float xc = xv[c];
                const float4* wp = (const float4*)(wbase + c*HID);
                float4 w0 = wp[0], w1 = wp[1], w2 = wp[2], w3 = wp[3];
                acc[0]  = fmaf(w0.x, xc, acc[0]);  acc[1]  = fmaf(w0.y, xc, acc[1]);
                acc[2]  = fmaf(w0.z, xc, acc[2]);  acc[3]  = fmaf(w0.w, xc, acc[3]);
                acc[4]  = fmaf(w1.x, xc, acc[4]);  acc[5]  = fmaf(w1.y, xc, acc[5]);
                acc[6]  = fmaf(w1.z, xc, acc[6]);  acc[7]  = fmaf(w1.w, xc, acc[7]);
                acc[8]  = fmaf(w2.x, xc, acc[8]);  acc[9]  = fmaf(w2.y, xc, acc[9]);
                acc[10] = fmaf(w2.z, xc, acc[10]); acc[11] = fmaf(w2.w, xc, acc[11]);
                acc[12] = fmaf(w3.x, xc, acc[12]); acc[13] = fmaf(w3.y, xc, acc[13]);
                acc[14] = fmaf(w3.z, xc, acc[14]); acc[15] = fmaf(w3.w, xc, acc[15]);
            }
            #pragma unroll
            for (int i = 0; i < 16; i++) sh_h[(hb + i)*NPIX + pp] = acc[i];
        }
    }
    __syncthreads();

    // Swap weights: sh_w now holds w_out as [hid][o] (broadcast LDS.128 later)
    for (int i = tid; i < 64*HID; i += 256) {
        int o = i / HID, hid = i % HID;
        sh_w[hid*64 + o] = w_out[i];
    }
    __syncthreads();

    // --------- Phase 2: depthwise 3x3 + LeakyReLU + project_out ------------
    {
        const int ix = tid & 15, iy = tid >> 4;
        const int pp = (iy + 1)*PAD + (ix + 1);
        float acc[64];
        #pragma unroll
        for (int o = 0; o < 64; o++) acc[o] = sh_bout[o];

        #pragma unroll 1
        for (int hb = 0; hb < HID; hb += 8) {
            float yv[8];
            #pragma unroll
            for (int i = 0; i < 8; i++) {
                int hid = hb + i;
                const float* hp = sh_h + hid*NPIX + pp;
                const float* kp = sh_ker + hid*9;
                float s;
                s = kp[0] * hp[-PAD-1];
                s = fmaf(kp[1], hp[-PAD  ], s);
                s = fmaf(kp[2], hp[-PAD+1], s);
                s = fmaf(kp[3], hp[-1    ], s);
                s = fmaf(kp[4], hp[ 0    ], s);
                s = fmaf(kp[5], hp[ 1    ], s);
                s = fmaf(kp[6], hp[ PAD-1], s);
                s = fmaf(kp[7], hp[ PAD  ], s);
                s = fmaf(kp[8], hp[ PAD+1], s);
                yv[i] = s > 0.f ? s : 0.1f * s;   // LeakyReLU(0.1)
            }
            #pragma unroll
            for (int i = 0; i < 8; i++) {
                const float4* wp = (const float4*)(sh_w + (hb + i)*64);
                float y = yv[i];
                #pragma unroll
                for (int q = 0; q < 16; q++) {
                    float4 w4 = wp[q];
                    acc[q*4+0] = fmaf(w4.x, y, acc[q*4+0]);
                    acc[q*4+1] = fmaf(w4.y, y, acc[q*4+1]);
                    acc[q*4+2] = fmaf(w4.z, y, acc[q*4+2]);
                    acc[q*4+3] = fmaf(w4.w, y, acc[q*4+3]);
                }
            }
        }

        const int gy = ty0 + iy, gx = tx0 + ix;
        float* op = out + (size_t)b * DIM * HW + gy*WW + gx;
        #pragma unroll
        for (int o = 0; o < 64; o++) op[(size_t)o * HW] = acc[o];
    }
}

// ---------------------------------------------------------------------------
extern "C" void kernel_launch(void* const* d_in, const int* in_sizes, int n_in,
                              void* d_out, int out_size) {
    const float* x     = (const float*)d_in[0];
    const float* w_in  = (const float*)d_in[1];
    const float* b_in  = (const float*)d_in[2];
    const float* wg1   = (const float*)d_in[3];
    const float* bg1   = (const float*)d_in[4];
    const float* wg2   = (const float*)d_in[5];
    const float* bg2   = (const float*)d_in[6];
    const float* w_out = (const float*)d_in[7];
    const float* b_out = (const float*)d_in[8];
    float* out = (float*)d_out;

    const int SMEM_BYTES = (8192 + HID*9 + HID + 64 + HID*NPIX) * sizeof(float); // 204032
    cudaFuncSetAttribute(k_main, cudaFuncAttributeMaxDynamicSharedMemorySize, SMEM_BYTES);

    k_mean<<<B_*DIM, 256>>>(x);
    k_gen<<<B_, HID>>>(w_in, b_in, wg1, bg1, wg2, bg2);
    dim3 grid(WW/TS, HH/TS, B_);
    k_main<<<grid, 256, SMEM_BYTES>>>(x, w_in, b_in, w_out, b_out, out);
}

// round 2
// speedup vs baseline: 1.1062x; 1.1062x over previous
#include <cuda_runtime.h>

// Problem constants (fixed shapes from reference)
#define B_    8
#define DIM   64
#define HID   128
#define HH    192
#define WW    192
#define HW    (HH*WW)          // 36864
#define TS    16               // interior tile
#define PAD   18               // TS + 2 halo
#define NPIX  (PAD*PAD)        // 324

typedef unsigned long long ull;

// packed f32x2 helpers (ptxas never emits FFMA2 from C++ — PTX only)
__device__ __forceinline__ ull ffma2(ull a, ull b, ull c) {
    ull d;
    asm("fma.rn.f32x2 %0, %1, %2, %3;" : "=l"(d) : "l"(a), "l"(b), "l"(c));
    return d;
}
__device__ __forceinline__ ull pack2(float x) {           // (x, x)
    ull r;
    asm("mov.b64 %0, {%1, %1};" : "=l"(r) : "f"(x));
    return r;
}
__device__ __forceinline__ void unpack2(ull v, float& lo, float& hi) {
    asm("mov.b64 {%0, %1}, %2;" : "=f"(lo), "=f"(hi) : "l"(v));
}

// Scratch (no device mallocs allowed)
__device__ float g_xmean[B_*DIM];
__device__ float g_ker[B_*HID*9];

// ---------------------------------------------------------------------------
// Kernel 1: per-(b,c) spatial mean of x. grid = B*DIM blocks, 256 threads.
// ---------------------------------------------------------------------------
__global__ void k_mean(const float* __restrict__ x) {
    int bc = blockIdx.x;
    const float4* p = (const float4*)(x + (size_t)bc * HW);
    float s = 0.f;
    #pragma unroll 4
    for (int i = threadIdx.x; i < HW/4; i += 256) {
        float4 v = p[i];
        s += (v.x + v.y) + (v.z + v.w);
    }
    __shared__ float red[8];
    #pragma unroll
    for (int o = 16; o; o >>= 1) s += __shfl_down_sync(0xffffffffu, s, o);
    if ((threadIdx.x & 31) == 0) red[threadIdx.x >> 5] = s;
    __syncthreads();
    if (threadIdx.x < 32) {
        s = (threadIdx.x < 8) ? red[threadIdx.x] : 0.f;
        #pragma unroll
        for (int o = 4; o; o >>= 1) s += __shfl_down_sync(0xffffffffu, s, o);
        if (threadIdx.x == 0) g_xmean[bc] = s * (1.0f / (float)HW);
    }
}

// ---------------------------------------------------------------------------
// Kernel 2: dynamic 3x3 kernel generation (mean(h) = w_in @ mean(x) + b_in).
// ---------------------------------------------------------------------------
__global__ void k_gen(const float* __restrict__ w_in, const float* __restrict__ b_in,
                      const float* __restrict__ wg1,  const float* __restrict__ bg1,
                      const float* __restrict__ wg2,  const float* __restrict__ bg2) {
    int b = blockIdx.x;
    int t = threadIdx.x;  // 0..127
    __shared__ float xm[DIM], g0[HID], g1[HID];
    if (t < DIM) xm[t] = g_xmean[b*DIM + t];
    __syncthreads();
    {
        float s = b_in[t];
        #pragma unroll 8
        for (int c = 0; c < DIM; c++) s = fmaf(w_in[t*DIM + c], xm[c], s);
        g0[t] = s;
    }
    __syncthreads();
    {
        float s = bg1[t];
        #pragma unroll 8
        for (int c = 0; c < HID; c++) s = fmaf(wg1[t*HID + c], g0[c], s);
        g1[t] = s > 0.f ? s : 0.f;
    }
    __syncthreads();
    #pragma unroll
    for (int tt = 0; tt < 9; tt++) {
        int row = t*9 + tt;
        float s = bg2[row];
        #pragma unroll 8
        for (int c = 0; c < HID; c++) s = fmaf(wg2[row*HID + c], g1[c], s);
        g_ker[b*HID*9 + row] = s;
    }
}

// ---------------------------------------------------------------------------
// Kernel 3: fused  h = w_in@x + b_in  ->  per-sample depthwise 3x3 (SAME) ->
// LeakyReLU(0.1) -> out = w_out@y + b_out.  FFMA2 (f32x2) everywhere hot.
//
// SMEM layout (floats):
//   sh_w   [8192]   : phase1 = w_in transposed [c][hid]; phase2 = w_out [hid][o]
//   sh_ker [1152], sh_bin [128], sh_bout [64]
//   sh_h   [HID*NPIX = 41472]
// ---------------------------------------------------------------------------
extern __shared__ float smem[];

__global__ __launch_bounds__(256, 1)
void k_main(const float* __restrict__ x,
            const float* __restrict__ w_in,  const float* __restrict__ b_in,
            const float* __restrict__ w_out, const float* __restrict__ b_out,
            float* __restrict__ out) {
    float* sh_w    = smem;
    float* sh_ker  = smem + 8192;
    float* sh_bin  = sh_ker + HID*9;
    float* sh_bout = sh_bin + HID;
    float* sh_h    = sh_bout + 64;

    const int tid = threadIdx.x;
    const int b   = blockIdx.z;
    const int tx0 = blockIdx.x * TS, ty0 = blockIdx.y * TS;

    // --- load phase-1 weights: w_in transposed so inner loop does LDS.128 ---
    for (int i = tid; i < HID*DIM; i += 256) {
        int o = i / DIM, c = i % DIM;
        sh_w[c*HID + o] = w_in[i];
    }
    if (tid < HID) sh_bin[tid]  = b_in[tid];
    if (tid < 64)  sh_bout[tid] = b_out[tid];
    for (int i = tid; i < HID*9; i += 256) sh_ker[i] = g_ker[b*HID*9 + i];
    __syncthreads();

    // ------------------------- Phase 1: h into SMEM -------------------------
    const float* xb = x + (size_t)b * DIM * HW;
    for (int it = 0; it < 2; it++) {
        int pp = tid + it*256;
        if (pp >= NPIX) break;
        int py = pp / PAD, px = pp % PAD;
        int gy = ty0 + py - 1, gx = tx0 + px - 1;
        bool valid = (gy >= 0) & (gy < HH) & (gx >= 0) & (gx < WW);

        float xv[DIM];
        const float* xp = xb + gy*WW + gx;
        #pragma unroll
        for (int c = 0; c < DIM; c++) xv[c] = valid ? xp[(size_t)c * HW] : 0.f;

        #pragma unroll 1
        for (int hb = 0; hb < HID; hb += 32) {
            ull acc2[16];                       // 16 pairs = 32 hid channels
            const ull* bp = (const ull*)(sh_bin + hb);
            #pragma unroll
            for (int i = 0; i < 16; i++) acc2[i] = valid ? bp[i] : 0ull;

            const float* wbase = sh_w + hb;
            #pragma unroll 8
            for (int c = 0; c < DIM; c++) {
                ull xx = pack2(xv[c]);
                const ulonglong2* wp = (const ulonglong2*)(wbase + c*HID);
                #pragma unroll
                for (int j = 0; j < 8; j++) {
                    ulonglong2 w2 = wp[j];
                    acc2[2*j]   = ffma2(w2.x, xx, acc2[2*j]);
                    acc2[2*j+1] = ffma2(w2.y, xx, acc2[2*j+1]);
                }
            }
            #pragma unroll
            for (int i = 0; i < 16; i++) {
                float lo, hi;
                unpack2(acc2[i], lo, hi);
                sh_h[(hb + 2*i    )*NPIX + pp] = lo;
                sh_h[(hb + 2*i + 1)*NPIX + pp] = hi;
            }
        }
    }
    __syncthreads();

    // Swap weights: sh_w now holds w_out as [hid][o]
    for (int i = tid; i < 64*HID; i += 256) {
        int o = i / HID, hid = i % HID;
        sh_w[hid*64 + o] = w_out[i];
    }
    __syncthreads();

    // --------- Phase 2: depthwise 3x3 + LeakyReLU + project_out ------------
    {
        const int ix = tid & 15, iy = tid >> 4;
        const int pp = (iy + 1)*PAD + (ix + 1);
        ull acc2[32];                           // 32 pairs = 64 output channels
        const ull* bop = (const ull*)sh_bout;
        #pragma unroll
        for (int i = 0; i < 32; i++) acc2[i] = bop[i];

        #pragma unroll 1
        for (int hb = 0; hb < HID; hb += 8) {
            float yv[8];
            #pragma unroll
            for (int i = 0; i < 8; i++) {
                int hid = hb + i;
                const float* hp = sh_h + hid*NPIX + pp;
                const float* kp = sh_ker + hid*9;
                float s;
                s = kp[0] * hp[-PAD-1];
                s = fmaf(kp[1], hp[-PAD  ], s);
                s = fmaf(kp[2], hp[-PAD+1], s);
                s = fmaf(kp[3], hp[-1    ], s);
                s = fmaf(kp[4], hp[ 0    ], s);
                s = fmaf(kp[5], hp[ 1    ], s);
                s = fmaf(kp[6], hp[ PAD-1], s);
                s = fmaf(kp[7], hp[ PAD  ], s);
                s = fmaf(kp[8], hp[ PAD+1], s);
                yv[i] = s > 0.f ? s : 0.1f * s;   // LeakyReLU(0.1)
            }
            #pragma unroll
            for (int i = 0; i < 8; i++) {
                ull yy = pack2(yv[i]);
                const ulonglong2* wp = (const ulonglong2*)(sh_w + (hb + i)*64);
                #pragma unroll
                for (int j = 0; j < 16; j++) {
                    ulonglong2 w2 = wp[j];
                    acc2[2*j]   = ffma2(w2.x, yy, acc2[2*j]);
                    acc2[2*j+1] = ffma2(w2.y, yy, acc2[2*j+1]);
                }
            }
        }

        const int gy = ty0 + iy, gx = tx0 + ix;
        float* op = out + (size_t)b * DIM * HW + gy*WW + gx;
        #pragma unroll
        for (int j = 0; j < 32; j++) {
            float lo, hi;
            unpack2(acc2[j], lo, hi);
            op[(size_t)(2*j    ) * HW] = lo;
            op[(size_t)(2*j + 1) * HW] = hi;
        }
    }
}

// ---------------------------------------------------------------------------
extern "C" void kernel_launch(void* const* d_in, const int* in_sizes, int n_in,
                              void* d_out, int out_size) {
    const float* x     = (const float*)d_in[0];
    const float* w_in  = (const float*)d_in[1];
    const float* b_in  = (const float*)d_in[2];
    const float* wg1   = (const float*)d_in[3];
    const float* bg1   = (const float*)d_in[4];
    const float* wg2   = (const float*)d_in[5];
    const float* bg2   = (const float*)d_in[6];
    const float* w_out = (const float*)d_in[7];
    const float* b_out = (const float*)d_in[8];
    float* out = (float*)d_out;

    const int SMEM_BYTES = (8192 + HID*9 + HID + 64 + HID*NPIX) * sizeof(float); // 204032
    cudaFuncSetAttribute(k_main, cudaFuncAttributeMaxDynamicSharedMemorySize, SMEM_BYTES);

    k_mean<<<B_*DIM, 256>>>(x);
    k_gen<<<B_, HID>>>(w_in, b_in, wg1, bg1, wg2, bg2);
    dim3 grid(WW/TS, HH/TS, B_);
    k_main<<<grid, 256, SMEM_BYTES>>>(x, w_in, b_in, w_out, b_out, out);
}